// round 2
// baseline (speedup 1.0000x reference)
#include <cuda_runtime.h>
#include <math.h>

#define NN 20000
#define NE 320000
#define HD 512
#define NG 64
#define V4 128                         // float4 per 512-float row
#define NBLK 148
#define CHUNK ((NN + NBLK - 1) / NBLK) // 136

// ---------------- device scratch ----------------
__device__ int g_degD[NN], g_degS[NN];
__device__ int g_curD[NN], g_curS[NN];
__device__ int g_offD[NN + 1], g_offS[NN + 1];
__device__ int g_srcByDst[NE];    // src node ids grouped by dst (in-edges CSR)
__device__ int g_graphBySrc[NE];  // batch[dst] grouped by src (out-edge graph CSR)
__device__ int g_n[NG], g_m[NG];
__device__ float g_part[(size_t)NBLK * NG * HD];  // 19.4 MB per-block partials
__device__ float g_U[NG * HD], g_P[NG * HD], g_pooled[NG * HD];

__device__ __forceinline__ float4 f4add(float4 a, float4 b) {
    a.x += b.x; a.y += b.y; a.z += b.z; a.w += b.w; return a;
}

// ---------------- 1. zero counters ----------------
__global__ void k_init() {
    int i = blockIdx.x * blockDim.x + threadIdx.x;
    int stride = gridDim.x * blockDim.x;
    for (int j = i; j < NN; j += stride) { g_degD[j] = 0; g_degS[j] = 0; g_curD[j] = 0; g_curS[j] = 0; }
    for (int j = i; j < NG; j += stride) { g_n[j] = 0; g_m[j] = 0; }
}

// ---------------- 2. histograms ----------------
__global__ void k_hist(const int* __restrict__ src, const int* __restrict__ dst,
                       const int* __restrict__ batch) {
    int e = blockIdx.x * blockDim.x + threadIdx.x;
    if (e < NE) {
        int d = dst[e];
        int s = src[e];
        atomicAdd(&g_degD[d], 1);
        atomicAdd(&g_degS[s], 1);
        atomicAdd(&g_m[batch[d]], 1);
    }
    if (e < NN) {
        atomicAdd(&g_n[batch[e]], 1);
    }
}

// ---------------- 3. exclusive scans (both CSRs, single block) ----------------
__device__ void scan_one(const int* __restrict__ deg, int* __restrict__ off) {
    const int T = 1024;
    const int CH = (NN + T - 1) / T;  // 20
    __shared__ int sh[T];
    int t = threadIdx.x;
    int base = t * CH;
    int sum = 0;
    for (int j = 0; j < CH; j++) {
        int idx = base + j;
        if (idx < NN) sum += deg[idx];
    }
    sh[t] = sum;
    __syncthreads();
    for (int ofs = 1; ofs < T; ofs <<= 1) {
        int v = (t >= ofs) ? sh[t - ofs] : 0;
        __syncthreads();
        sh[t] += v;
        __syncthreads();
    }
    int run = (t == 0) ? 0 : sh[t - 1];
    for (int j = 0; j < CH; j++) {
        int idx = base + j;
        if (idx < NN) { off[idx] = run; run += deg[idx]; }
    }
    if (t == T - 1) off[NN] = run;
    __syncthreads();
}

__global__ void k_scan2() {
    scan_one(g_degD, g_offD);
    scan_one(g_degS, g_offS);
}

// ---------------- 4. CSR fill ----------------
__global__ void k_fill(const int* __restrict__ src, const int* __restrict__ dst,
                       const int* __restrict__ batch) {
    int e = blockIdx.x * blockDim.x + threadIdx.x;
    if (e < NE) {
        int d = dst[e];
        int s = src[e];
        int gb = batch[d];
        int p = g_offD[d] + atomicAdd(&g_curD[d], 1);
        g_srcByDst[p] = s;
        int q = g_offS[s] + atomicAdd(&g_curS[s], 1);
        g_graphBySrc[q] = gb;
    }
}

// ---------------- 5. fused: A_i in regs (pass-1 gather), smem scatter-by-count (pass-2) ----------------
__global__ void __launch_bounds__(128) k_fused(const float* __restrict__ x,
                                               const int* __restrict__ batch) {
    extern __shared__ float4 acc[];  // [NG * V4] = 128 KB
    int t = threadIdx.x;
    // each thread zeroes exactly its own columns (k ≡ t mod 128) — no sync needed
    for (int k = t; k < NG * V4; k += 128) acc[k] = make_float4(0.f, 0.f, 0.f, 0.f);

    const float4* __restrict__ x4 = (const float4*)x;
    int i0 = blockIdx.x * CHUNK;
    int i1 = i0 + CHUNK; if (i1 > NN) i1 = NN;

    for (int i = i0; i < i1; i++) {
        // ---- A_i = x_i + sum_{in-edges} x_src  (random L2 gather, 4-way MLP) ----
        float4 a0 = x4[(size_t)i * V4 + t];
        float4 a1 = make_float4(0.f, 0.f, 0.f, 0.f);
        float4 a2 = a1, a3 = a1;
        int e0 = g_offD[i], e1 = g_offD[i + 1];
        int e = e0;
        for (; e + 4 <= e1; e += 4) {
            int s0 = g_srcByDst[e];
            int s1 = g_srcByDst[e + 1];
            int s2 = g_srcByDst[e + 2];
            int s3 = g_srcByDst[e + 3];
            float4 v0 = x4[(size_t)s0 * V4 + t];
            float4 v1 = x4[(size_t)s1 * V4 + t];
            float4 v2 = x4[(size_t)s2 * V4 + t];
            float4 v3 = x4[(size_t)s3 * V4 + t];
            a0 = f4add(a0, v0);
            a1 = f4add(a1, v1);
            a2 = f4add(a2, v2);
            a3 = f4add(a3, v3);
        }
        for (; e < e1; e++) {
            int s = g_srcByDst[e];
            a0 = f4add(a0, x4[(size_t)s * V4 + t]);
        }
        float4 a = f4add(f4add(a0, a1), f4add(a2, a3));

        // ---- direct term: acc[batch[i]] += A_i ----
        int gb = batch[i];
        acc[gb * V4 + t] = f4add(acc[gb * V4 + t], a);

        // ---- scatter term: for each out-edge, acc[graph(dst)] += A_i ----
        int f0 = g_offS[i], f1 = g_offS[i + 1];
        int f = f0;
        for (; f + 4 <= f1; f += 4) {
            int ga = g_graphBySrc[f];
            int gB = g_graphBySrc[f + 1];
            int gc = g_graphBySrc[f + 2];
            int gd = g_graphBySrc[f + 3];
            acc[ga * V4 + t] = f4add(acc[ga * V4 + t], a);
            acc[gB * V4 + t] = f4add(acc[gB * V4 + t], a);
            acc[gc * V4 + t] = f4add(acc[gc * V4 + t], a);
            acc[gd * V4 + t] = f4add(acc[gd * V4 + t], a);
        }
        for (; f < f1; f++) {
            int g = g_graphBySrc[f];
            acc[g * V4 + t] = f4add(acc[g * V4 + t], a);
        }
    }

    // write per-block partial (fully written — no pre-zero needed)
    float4* P = ((float4*)g_part) + (size_t)blockIdx.x * NG * V4;
    for (int k = t; k < NG * V4; k += 128) P[k] = acc[k];
}

// ---------------- 6. reduce partials -> U ----------------
__global__ void __launch_bounds__(128) k_reduceU() {
    int g = blockIdx.x;       // graph
    int t = threadIdx.x;      // float4 column
    const float4* P = (const float4*)g_part;
    float4 s0 = make_float4(0.f, 0.f, 0.f, 0.f), s1 = s0, s2 = s0, s3 = s0;
    int b = 0;
    for (; b + 4 <= NBLK; b += 4) {
        s0 = f4add(s0, P[(size_t)(b + 0) * NG * V4 + g * V4 + t]);
        s1 = f4add(s1, P[(size_t)(b + 1) * NG * V4 + g * V4 + t]);
        s2 = f4add(s2, P[(size_t)(b + 2) * NG * V4 + g * V4 + t]);
        s3 = f4add(s3, P[(size_t)(b + 3) * NG * V4 + g * V4 + t]);
    }
    for (; b < NBLK; b++) s0 = f4add(s0, P[(size_t)b * NG * V4 + g * V4 + t]);
    ((float4*)g_U)[g * V4 + t] = f4add(f4add(s0, s1), f4add(s2, s3));
}

// ---------------- 7. out[64,512] = in[64,512] @ W[512,512] + scale_g * bias ----------------
__global__ void __launch_bounds__(128) k_mm512(const float* __restrict__ in,
                                               const float* __restrict__ W,
                                               const float* __restrict__ bias,
                                               const int* __restrict__ s1,
                                               const int* __restrict__ s2,
                                               float* __restrict__ out) {
    __shared__ float sIn[HD];
    int g = blockIdx.y;
    int c = blockIdx.x * 128 + threadIdx.x;
    for (int k = threadIdx.x; k < HD; k += 128) sIn[k] = in[g * HD + k];
    __syncthreads();
    float acc = 0.f;
#pragma unroll 8
    for (int k = 0; k < HD; k++) acc += sIn[k] * W[k * HD + c];
    float sc = (float)(s1[g] + (s2 ? s2[g] : 0));
    out[g * HD + c] = acc + bias[c] * sc;
}

// ---------------- 8. classifier head ----------------
__global__ void __launch_bounds__(256) k_head(const float* __restrict__ Wc1,
                                              const float* __restrict__ bc1,
                                              const float* __restrict__ Wc2,
                                              const float* __restrict__ bc2,
                                              float* __restrict__ out) {
    int g = blockIdx.x;
    int j = threadIdx.x;  // 256 = HIDDEN/2
    __shared__ float sp[HD];
    for (int k = j; k < HD; k += 256) sp[k] = g_pooled[g * HD + k];
    __syncthreads();
    float acc = 0.f;
#pragma unroll 8
    for (int k = 0; k < HD; k++) acc += sp[k] * Wc1[k * 256 + j];
    float zj = fmaxf(acc + bc1[j], 0.f) * Wc2[j];
    __shared__ float red[256];
    red[j] = zj;
    __syncthreads();
    for (int ofs = 128; ofs > 0; ofs >>= 1) {
        if (j < ofs) red[j] += red[j + ofs];
        __syncthreads();
    }
    if (j == 0) {
        float s = red[0] + bc2[0];
        out[g] = 1.0f / (1.0f + expf(-s));
    }
}

// ---------------- launch ----------------
extern "C" void kernel_launch(void* const* d_in, const int* in_sizes, int n_in,
                              void* d_out, int out_size) {
    const float* x     = (const float*)d_in[0];
    const int*   ei    = (const int*)d_in[1];  // [2, E]
    const int*   batch = (const int*)d_in[2];
    const float* W_g1  = (const float*)d_in[3];
    const float* b_g1  = (const float*)d_in[4];
    const float* W_g2  = (const float*)d_in[5];
    const float* b_g2  = (const float*)d_in[6];
    const float* W_c1  = (const float*)d_in[7];
    const float* b_c1  = (const float*)d_in[8];
    const float* W_c2  = (const float*)d_in[9];
    const float* b_c2  = (const float*)d_in[10];
    float* out = (float*)d_out;

    const int* src = ei;
    const int* dst = ei + NE;

    float *pU, *pP, *pPooled;
    int *pn, *pm;
    cudaGetSymbolAddress((void**)&pU, g_U);
    cudaGetSymbolAddress((void**)&pP, g_P);
    cudaGetSymbolAddress((void**)&pPooled, g_pooled);
    cudaGetSymbolAddress((void**)&pn, g_n);
    cudaGetSymbolAddress((void**)&pm, g_m);

    cudaFuncSetAttribute(k_fused, cudaFuncAttributeMaxDynamicSharedMemorySize,
                         NG * V4 * (int)sizeof(float4));

    k_init<<<256, 256>>>();
    k_hist<<<(NE + 255) / 256, 256>>>(src, dst, batch);
    k_scan2<<<1, 1024>>>();
    k_fill<<<(NE + 255) / 256, 256>>>(src, dst, batch);
    k_fused<<<NBLK, 128, NG * V4 * (int)sizeof(float4)>>>(x, batch);
    k_reduceU<<<NG, 128>>>();
    // P = U @ W1 + (n+m)*b1
    k_mm512<<<dim3(HD / 128, NG), 128>>>(pU, W_g1, b_g1, pn, pm, pP);
    // pooled = P @ W2 + n*b2
    k_mm512<<<dim3(HD / 128, NG), 128>>>(pP, W_g2, b_g2, pn, (const int*)nullptr, pPooled);
    k_head<<<NG, 256>>>(W_c1, b_c1, W_c2, b_c2, out);
}

// round 3
// speedup vs baseline: 2.7095x; 2.7095x over previous
#include <cuda_runtime.h>
#include <math.h>

#define NN 20000
#define NE 320000
#define HD 512
#define NG 64

// GEMM partition
#define NKC 37            // K-chunks
#define KC  541           // nodes per K-chunk (37*541 = 20017 >= 20000)
#define TK  32            // k-tile
#define NCB 4             // column blocks of 128

// ---------------- device scratch ----------------
__device__ int   g_degS[NN], g_curS[NN];
__device__ int   g_offS[NN + 1];
__device__ int   g_dstBySrc[NE];       // dst ids grouped by src
__device__ int   g_w[NN * NG];         // w-hat counts  (5.1 MB)
__device__ float g_v[NN * NG];         // GEMM left operand (5.1 MB)
__device__ int   g_n[NG], g_m[NG];
__device__ float g_part[(size_t)(NKC * NCB) * NG * 128];  // 4.85 MB partials
__device__ float g_U[NG * HD], g_P[NG * HD], g_pooled[NG * HD];

__device__ __forceinline__ void cp_async16(void* smem, const void* gmem) {
    unsigned s = (unsigned)__cvta_generic_to_shared(smem);
    asm volatile("cp.async.cg.shared.global [%0], [%1], 16;" :: "r"(s), "l"(gmem));
}

// ---------------- 1. zero counters + w table ----------------
__global__ void k_init() {
    int i = blockIdx.x * blockDim.x + threadIdx.x;
    int stride = gridDim.x * blockDim.x;
    for (int j = i; j < NN; j += stride) { g_degS[j] = 0; g_curS[j] = 0; }
    for (int j = i; j < NG; j += stride) { g_n[j] = 0; g_m[j] = 0; }
    for (int j = i; j < NN * NG; j += stride) g_w[j] = 0;
}

// ---------------- 2. histograms: out-degree, n, m, w-hat ----------------
__global__ void k_hist(const int* __restrict__ src, const int* __restrict__ dst,
                       const int* __restrict__ batch) {
    int e = blockIdx.x * blockDim.x + threadIdx.x;
    if (e < NE) {
        int s = src[e];
        int d = dst[e];
        int gb = batch[d];
        atomicAdd(&g_degS[s], 1);
        atomicAdd(&g_m[gb], 1);
        atomicAdd(&g_w[s * NG + gb], 1);      // out-edge count term
    }
    if (e < NN) {
        int gb = batch[e];
        atomicAdd(&g_n[gb], 1);
        atomicAdd(&g_w[e * NG + gb], 1);      // self (direct) term
    }
}

// ---------------- 3. exclusive scan of out-degrees (single block) ----------------
__global__ void k_scan() {
    const int T = 1024;
    const int CH = (NN + T - 1) / T;  // 20
    __shared__ int sh[T];
    int t = threadIdx.x;
    int base = t * CH;
    int sum = 0;
    for (int j = 0; j < CH; j++) {
        int idx = base + j;
        if (idx < NN) sum += g_degS[idx];
    }
    sh[t] = sum;
    __syncthreads();
    for (int ofs = 1; ofs < T; ofs <<= 1) {
        int v = (t >= ofs) ? sh[t - ofs] : 0;
        __syncthreads();
        sh[t] += v;
        __syncthreads();
    }
    int run = (t == 0) ? 0 : sh[t - 1];
    for (int j = 0; j < CH; j++) {
        int idx = base + j;
        if (idx < NN) { g_offS[idx] = run; run += g_degS[idx]; }
    }
    if (t == T - 1) g_offS[NN] = run;
}

// ---------------- 4. CSR fill (src-grouped dst list) ----------------
__global__ void k_fill(const int* __restrict__ src, const int* __restrict__ dst) {
    int e = blockIdx.x * blockDim.x + threadIdx.x;
    if (e < NE) {
        int s = src[e];
        int d = dst[e];
        int q = g_offS[s] + atomicAdd(&g_curS[s], 1);
        g_dstBySrc[q] = d;
    }
}

// ---------------- 5. v[i,:] = w[i,:] + sum_{out-edges i->d} w[d,:]  (warp per node) ----------------
__global__ void __launch_bounds__(256) k_vgather() {
    int i = (blockIdx.x * 256 + threadIdx.x) >> 5;   // node id
    int lane = threadIdx.x & 31;
    if (i >= NN) return;
    const int2* __restrict__ w2 = (const int2*)g_w;  // 32 int2 per row
    int2 a = w2[(size_t)i * 32 + lane];
    int ax = a.x, ay = a.y;
    int bx = 0, by = 0, cx = 0, cy = 0, dx = 0, dy = 0;
    int f0 = g_offS[i], f1 = g_offS[i + 1];
    int f = f0;
    for (; f + 4 <= f1; f += 4) {
        int d0 = g_dstBySrc[f];
        int d1 = g_dstBySrc[f + 1];
        int d2 = g_dstBySrc[f + 2];
        int d3 = g_dstBySrc[f + 3];
        int2 t0 = w2[(size_t)d0 * 32 + lane];
        int2 t1 = w2[(size_t)d1 * 32 + lane];
        int2 t2 = w2[(size_t)d2 * 32 + lane];
        int2 t3 = w2[(size_t)d3 * 32 + lane];
        ax += t0.x; ay += t0.y;
        bx += t1.x; by += t1.y;
        cx += t2.x; cy += t2.y;
        dx += t3.x; dy += t3.y;
    }
    for (; f < f1; f++) {
        int d0 = g_dstBySrc[f];
        int2 t0 = w2[(size_t)d0 * 32 + lane];
        ax += t0.x; ay += t0.y;
    }
    ax += bx + cx + dx;
    ay += by + cy + dy;
    ((float2*)g_v)[(size_t)i * 32 + lane] = make_float2((float)ax, (float)ay);
}

// ---------------- 6. U-GEMM: part[kc,cb] = v[kchunk,64]^T @ x[kchunk,128cols] ----------------
__global__ void __launch_bounds__(256) k_gemmU(const float* __restrict__ x) {
    int kc = blockIdx.x >> 2;
    int cb = blockIdx.x & 3;
    int k0 = kc * KC;
    int k1 = k0 + KC; if (k1 > NN) k1 = NN;

    __shared__ float sx[2][TK][128];   // 16 KB per buffer
    __shared__ float sv[2][TK][NG];    //  8 KB per buffer

    int tid = threadIdx.x;
    int cq = tid & 15;    // column group (8 cols each)
    int gg = tid >> 4;    // graph group (4 graphs each)

    float4 acc[4][2];
#pragma unroll
    for (int j = 0; j < 4; j++) {
        acc[j][0] = make_float4(0.f, 0.f, 0.f, 0.f);
        acc[j][1] = make_float4(0.f, 0.f, 0.f, 0.f);
    }

    int NT = (k1 - k0 + TK - 1) / TK;

#define LOAD_TILE(T_, B_)                                                        \
    {                                                                            \
        int kt = k0 + (T_) * TK;                                                 \
        _Pragma("unroll")                                                        \
        for (int j = 0; j < 4; j++) {                                            \
            int lin = tid + j * 256;                                             \
            int kk = lin >> 5, cc = lin & 31;                                    \
            float* sp = &sx[B_][kk][cc * 4];                                     \
            if (kt + kk < k1)                                                    \
                cp_async16(sp, x + (size_t)(kt + kk) * HD + cb * 128 + cc * 4);  \
            else                                                                 \
                *(float4*)sp = make_float4(0.f, 0.f, 0.f, 0.f);                  \
        }                                                                        \
        _Pragma("unroll")                                                        \
        for (int j = 0; j < 2; j++) {                                            \
            int lin = tid + j * 256;                                             \
            int kk = lin >> 4, cc = lin & 15;                                    \
            float* sp = &sv[B_][kk][cc * 4];                                     \
            if (kt + kk < k1)                                                    \
                cp_async16(sp, g_v + (size_t)(kt + kk) * NG + cc * 4);           \
            else                                                                 \
                *(float4*)sp = make_float4(0.f, 0.f, 0.f, 0.f);                  \
        }                                                                        \
        asm volatile("cp.async.commit_group;");                                  \
    }

    LOAD_TILE(0, 0);
    for (int t = 0; t < NT; t++) {
        int b = t & 1;
        if (t + 1 < NT) {
            LOAD_TILE(t + 1, b ^ 1);
            asm volatile("cp.async.wait_group 1;");
        } else {
            asm volatile("cp.async.wait_group 0;");
        }
        __syncthreads();
#pragma unroll 4
        for (int k = 0; k < TK; k++) {
            float4 x0 = *(float4*)&sx[b][k][cq * 8];
            float4 x1 = *(float4*)&sx[b][k][cq * 8 + 4];
            float4 vv = *(float4*)&sv[b][k][gg * 4];
#pragma unroll
            for (int j = 0; j < 4; j++) {
                float w = (j == 0) ? vv.x : (j == 1) ? vv.y : (j == 2) ? vv.z : vv.w;
                acc[j][0].x += w * x0.x; acc[j][0].y += w * x0.y;
                acc[j][0].z += w * x0.z; acc[j][0].w += w * x0.w;
                acc[j][1].x += w * x1.x; acc[j][1].y += w * x1.y;
                acc[j][1].z += w * x1.z; acc[j][1].w += w * x1.w;
            }
        }
        __syncthreads();
    }

    float* P = g_part + (size_t)blockIdx.x * NG * 128;
#pragma unroll
    for (int j = 0; j < 4; j++) {
        int g = gg * 4 + j;
        *(float4*)&P[g * 128 + cq * 8] = acc[j][0];
        *(float4*)&P[g * 128 + cq * 8 + 4] = acc[j][1];
    }
#undef LOAD_TILE
}

// ---------------- 7. reduce partials over K-chunks -> U ----------------
__global__ void __launch_bounds__(32) k_reduceU() {
    int g  = blockIdx.x >> 2;
    int cb = blockIdx.x & 3;
    int c4 = threadIdx.x;  // 0..31 float4 within 128 cols
    float4 s = make_float4(0.f, 0.f, 0.f, 0.f);
    for (int kc = 0; kc < NKC; kc++) {
        const float4* p = (const float4*)&g_part[(size_t)(kc * NCB + cb) * NG * 128 + g * 128 + c4 * 4];
        float4 t = *p;
        s.x += t.x; s.y += t.y; s.z += t.z; s.w += t.w;
    }
    *(float4*)&g_U[g * HD + cb * 128 + c4 * 4] = s;
}

// ---------------- 8. out[64,512] = in[64,512] @ W[512,512] + scale_g * bias ----------------
__global__ void __launch_bounds__(128) k_mm512(const float* __restrict__ in,
                                               const float* __restrict__ W,
                                               const float* __restrict__ bias,
                                               const int* __restrict__ s1,
                                               const int* __restrict__ s2,
                                               float* __restrict__ out) {
    __shared__ float sIn[HD];
    int g = blockIdx.y;
    int c = blockIdx.x * 128 + threadIdx.x;
    for (int k = threadIdx.x; k < HD; k += 128) sIn[k] = in[g * HD + k];
    __syncthreads();
    float acc = 0.f;
#pragma unroll 8
    for (int k = 0; k < HD; k++) acc += sIn[k] * W[k * HD + c];
    float sc = (float)(s1[g] + (s2 ? s2[g] : 0));
    out[g * HD + c] = acc + bias[c] * sc;
}

// ---------------- 9. classifier head ----------------
__global__ void __launch_bounds__(256) k_head(const float* __restrict__ Wc1,
                                              const float* __restrict__ bc1,
                                              const float* __restrict__ Wc2,
                                              const float* __restrict__ bc2,
                                              float* __restrict__ out) {
    int g = blockIdx.x;
    int j = threadIdx.x;  // 256 = HIDDEN/2
    __shared__ float sp[HD];
    for (int k = j; k < HD; k += 256) sp[k] = g_pooled[g * HD + k];
    __syncthreads();
    float acc = 0.f;
#pragma unroll 8
    for (int k = 0; k < HD; k++) acc += sp[k] * Wc1[k * 256 + j];
    float zj = fmaxf(acc + bc1[j], 0.f) * Wc2[j];
    __shared__ float red[256];
    red[j] = zj;
    __syncthreads();
    for (int ofs = 128; ofs > 0; ofs >>= 1) {
        if (j < ofs) red[j] += red[j + ofs];
        __syncthreads();
    }
    if (j == 0) {
        float s = red[0] + bc2[0];
        out[g] = 1.0f / (1.0f + expf(-s));
    }
}

// ---------------- launch ----------------
extern "C" void kernel_launch(void* const* d_in, const int* in_sizes, int n_in,
                              void* d_out, int out_size) {
    const float* x     = (const float*)d_in[0];
    const int*   ei    = (const int*)d_in[1];  // [2, E]
    const int*   batch = (const int*)d_in[2];
    const float* W_g1  = (const float*)d_in[3];
    const float* b_g1  = (const float*)d_in[4];
    const float* W_g2  = (const float*)d_in[5];
    const float* b_g2  = (const float*)d_in[6];
    const float* W_c1  = (const float*)d_in[7];
    const float* b_c1  = (const float*)d_in[8];
    const float* W_c2  = (const float*)d_in[9];
    const float* b_c2  = (const float*)d_in[10];
    float* out = (float*)d_out;

    const int* src = ei;
    const int* dst = ei + NE;

    float *pU, *pP, *pPooled;
    int *pn, *pm;
    cudaGetSymbolAddress((void**)&pU, g_U);
    cudaGetSymbolAddress((void**)&pP, g_P);
    cudaGetSymbolAddress((void**)&pPooled, g_pooled);
    cudaGetSymbolAddress((void**)&pn, g_n);
    cudaGetSymbolAddress((void**)&pm, g_m);

    k_init<<<256, 256>>>();
    k_hist<<<(NE + 255) / 256, 256>>>(src, dst, batch);
    k_scan<<<1, 1024>>>();
    k_fill<<<(NE + 255) / 256, 256>>>(src, dst);
    k_vgather<<<(NN * 32 + 255) / 256, 256>>>();
    k_gemmU<<<NKC * NCB, 256>>>(x);
    k_reduceU<<<NG * NCB, 32>>>();
    // P = U @ W1 + (n+m)*b1
    k_mm512<<<dim3(HD / 128, NG), 128>>>(pU, W_g1, b_g1, pn, pm, pP);
    // pooled = P @ W2 + n*b2
    k_mm512<<<dim3(HD / 128, NG), 128>>>(pP, W_g2, b_g2, pn, (const int*)nullptr, pPooled);
    k_head<<<NG, 256>>>(W_c1, b_c1, W_c2, b_c2, out);
}